// round 2
// baseline (speedup 1.0000x reference)
#include <cuda_runtime.h>
#include <cstdint>

#define NF   40
#define ED   128
#define AD   128
#define NP   780     // 40*39/2
#define NPP  784     // padded to 98 n-tiles of 8 pairs
#define NTHR 256
#define XST  132     // padded row stride for x in smem (conflict-free LDS)

__device__ __forceinline__ uint32_t tf32_of(float f) {
    uint32_t r;
    asm("cvt.rna.tf32.f32 %0, %1;" : "=r"(r) : "f"(f));
    return r;
}

// D(m16n8) += A(m16k8, tf32, row) * B(k8n8, tf32, col), fp32 accum
__device__ __forceinline__ void mma8(float* d, const uint32_t* a, uint32_t b0, uint32_t b1) {
    asm volatile(
        "mma.sync.aligned.m16n8k8.row.col.f32.tf32.tf32.f32 "
        "{%0,%1,%2,%3}, {%4,%5,%6,%7}, {%8,%9}, {%0,%1,%2,%3};"
        : "+f"(d[0]), "+f"(d[1]), "+f"(d[2]), "+f"(d[3])
        : "r"(a[0]), "r"(a[1]), "r"(a[2]), "r"(a[3]), "r"(b0), "r"(b1));
}

__global__ void __launch_bounds__(NTHR, 1)
afm_kernel(const float* __restrict__ x,    // [B, F, E]
           const float* __restrict__ ww,   // [A, E]
           const float* __restrict__ wb,   // [A]
           const float* __restrict__ hw,   // [1, A]
           const float* __restrict__ pw,   // [1, E]
           const float* __restrict__ pb,   // [1]
           float* __restrict__ out)        // [B]
{
    __shared__ float   xs[NF * XST];      // 21.1 KB
    __shared__ float   scs4[4][NPP];      // per-aslot partial scores
    __shared__ float   scs[NPP];
    __shared__ float   dvs[NPP];          // d[p] = hp_p . p_w
    __shared__ uint8_t pis[NPP], pjs[NPP];
    __shared__ float   red[24];

    const int tid  = threadIdx.x;
    const int wid  = tid >> 5, lane = tid & 31;
    const int g    = wid >> 2;        // pair-half: n-tiles [g*49, g*49+49)
    const int aslot = wid & 3;        // owns a-rows [aslot*32, aslot*32+32)
    const int q = lane >> 2, c = lane & 3;
    const int b = blockIdx.x;

    // ---- Stage x into padded smem ----
    const float* xg = x + (size_t)b * (NF * ED);
    for (int idx = tid; idx < NF * ED; idx += NTHR)
        xs[(idx >> 7) * XST + (idx & 127)] = xg[idx];

    // ---- Pair index tables (triu i<j, i-major) ----
    for (int p = tid; p < NPP; p += NTHR) {
        if (p < NP) {
            int i = 0, rem = p;
            while (rem >= NF - 1 - i) { rem -= NF - 1 - i; i++; }
            pis[p] = (uint8_t)i; pjs[p] = (uint8_t)(i + 1 + rem);
        } else { pis[p] = 0; pjs[p] = 1; }
    }

    // ---- W fragments: register-stationary for this warp's 32 a-rows ----
    const int A0 = aslot * 32;
    uint32_t wA[2][16][4];
    #pragma unroll
    for (int mt = 0; mt < 2; mt++) {
        #pragma unroll
        for (int s = 0; s < 16; s++) {
            int r0 = (A0 + mt * 16 + q) * ED;
            int r1 = r0 + 8 * ED;
            int k0 = s * 8 + c;
            wA[mt][s][0] = tf32_of(ww[r0 + k0]);
            wA[mt][s][1] = tf32_of(ww[r1 + k0]);
            wA[mt][s][2] = tf32_of(ww[r0 + k0 + 4]);
            wA[mt][s][3] = tf32_of(ww[r1 + k0 + 4]);
        }
    }
    float wbr[4], hr[4];
    #pragma unroll
    for (int u = 0; u < 4; u++) {
        wbr[u] = wb[A0 + u * 8 + q];
        hr[u]  = hw[A0 + u * 8 + q];
    }
    float pwr[4];
    #pragma unroll
    for (int k = 0; k < 4; k++) pwr[k] = pw[lane + 32 * k];

    __syncthreads();

    // ---- Main loop: 49 n-tiles of 8 pairs per warp ----
    for (int nt = g * 49; nt < g * 49 + 49; nt++) {
        const int p = nt * 8 + q;                 // this quad's pair (B col)
        const float* xi = &xs[(int)pis[p] * XST + c];
        const float* xj = &xs[(int)pjs[p] * XST + c];

        // hp fragments on the fly: brg[m] = hp[p][4m + c] as tf32
        uint32_t brg[32];
        #pragma unroll
        for (int m = 0; m < 32; m++)
            brg[m] = tf32_of(xi[4 * m] * xj[4 * m]);

        float acc0[4] = {0.f, 0.f, 0.f, 0.f};
        float acc1[4] = {0.f, 0.f, 0.f, 0.f};
        #pragma unroll
        for (int s = 0; s < 16; s++) {
            mma8(acc0, wA[0][s], brg[2 * s], brg[2 * s + 1]);
            mma8(acc1, wA[1][s], brg[2 * s], brg[2 * s + 1]);
        }

        // Fused epilogue: partial score = sum over this warp's 32 a of h*relu(.+wb)
        float s0 = fmaxf(acc0[0] + wbr[0], 0.f) * hr[0]
                 + fmaxf(acc0[2] + wbr[1], 0.f) * hr[1]
                 + fmaxf(acc1[0] + wbr[2], 0.f) * hr[2]
                 + fmaxf(acc1[2] + wbr[3], 0.f) * hr[3];
        float s1 = fmaxf(acc0[1] + wbr[0], 0.f) * hr[0]
                 + fmaxf(acc0[3] + wbr[1], 0.f) * hr[1]
                 + fmaxf(acc1[1] + wbr[2], 0.f) * hr[2]
                 + fmaxf(acc1[3] + wbr[3], 0.f) * hr[3];
        #pragma unroll
        for (int o = 4; o <= 16; o <<= 1) {
            s0 += __shfl_xor_sync(0xffffffffu, s0, o);
            s1 += __shfl_xor_sync(0xffffffffu, s1, o);
        }
        if (lane < 4) {
            scs4[aslot][nt * 8 + 2 * lane]     = s0;
            scs4[aslot][nt * 8 + 2 * lane + 1] = s1;
        }
    }

    // ---- d[p] = sum_e x_i,e * x_j,e * pw_e (warp per pair) ----
    for (int p = wid; p < NP; p += 8) {
        const float* xi = &xs[(int)pis[p] * XST];
        const float* xj = &xs[(int)pjs[p] * XST];
        float a = 0.f;
        #pragma unroll
        for (int k = 0; k < 4; k++) {
            int e = lane + 32 * k;
            a = fmaf(xi[e] * xj[e], pwr[k], a);
        }
        #pragma unroll
        for (int o = 16; o; o >>= 1) a += __shfl_xor_sync(0xffffffffu, a, o);
        if (lane == 0) dvs[p] = a;
    }
    __syncthreads();

    for (int p = tid; p < NP; p += NTHR)
        scs[p] = scs4[0][p] + scs4[1][p] + scs4[2][p] + scs4[3][p];
    __syncthreads();

    // ---- Softmax over pairs + weighted sum (h_b softmax-invariant, dropped) ----
    float lmax = -3.4e38f;
    for (int p = tid; p < NP; p += NTHR) lmax = fmaxf(lmax, scs[p]);
    #pragma unroll
    for (int o = 16; o; o >>= 1) lmax = fmaxf(lmax, __shfl_xor_sync(0xffffffffu, lmax, o));
    if (lane == 0) red[wid] = lmax;
    __syncthreads();
    float m = red[0];
    #pragma unroll
    for (int w = 1; w < 8; w++) m = fmaxf(m, red[w]);

    float se = 0.f, sd = 0.f;
    for (int p = tid; p < NP; p += NTHR) {
        float e = __expf(scs[p] - m);
        se += e;
        sd = fmaf(e, dvs[p], sd);
    }
    #pragma unroll
    for (int o = 16; o; o >>= 1) {
        se += __shfl_xor_sync(0xffffffffu, se, o);
        sd += __shfl_xor_sync(0xffffffffu, sd, o);
    }
    if (lane == 0) { red[8 + wid] = se; red[16 + wid] = sd; }
    __syncthreads();
    if (tid == 0) {
        float S = 0.f, D = 0.f;
        #pragma unroll
        for (int w = 0; w < 8; w++) { S += red[8 + w]; D += red[16 + w]; }
        out[b] = D / S + pb[0];
    }
}

extern "C" void kernel_launch(void* const* d_in, const int* in_sizes, int n_in,
                              void* d_out, int out_size) {
    const float* x  = (const float*)d_in[0];
    const float* ww = (const float*)d_in[1];
    const float* wb = (const float*)d_in[2];
    const float* hw = (const float*)d_in[3];
    // d_in[4] = attn_h_b: uniform shift on scores, softmax-invariant -> unused
    const float* pw = (const float*)d_in[5];
    const float* pb = (const float*)d_in[6];
    float* out = (float*)d_out;

    int B = in_sizes[0] / (NF * ED);
    afm_kernel<<<B, NTHR>>>(x, ww, wb, hw, pw, pb, out);
}

// round 3
// speedup vs baseline: 1.0816x; 1.0816x over previous
#include <cuda_runtime.h>
#include <cstdint>

#define NF   40
#define ED   128
#define AD   128
#define NP   780     // 40*39/2
#define NPP  784     // padded to 98 n-tiles of 8 pairs
#define NTHR 384     // 12 warps = 3 pair-groups x 4 a-slots
#define NWRP 12
#define XST  132     // padded row stride for x in smem (conflict-free LDS)

__device__ __forceinline__ uint32_t tf32_of(float f) {
    uint32_t r;
    asm("cvt.rna.tf32.f32 %0, %1;" : "=r"(r) : "f"(f));
    return r;
}

// D(m16n8) += A(m16k8, tf32, row) * B(k8n8, tf32, col), fp32 accum
__device__ __forceinline__ void mma8(float* d, const uint32_t* a, uint32_t b0, uint32_t b1) {
    asm volatile(
        "mma.sync.aligned.m16n8k8.row.col.f32.tf32.tf32.f32 "
        "{%0,%1,%2,%3}, {%4,%5,%6,%7}, {%8,%9}, {%0,%1,%2,%3};"
        : "+f"(d[0]), "+f"(d[1]), "+f"(d[2]), "+f"(d[3])
        : "r"(a[0]), "r"(a[1]), "r"(a[2]), "r"(a[3]), "r"(b0), "r"(b1));
}

__global__ void __launch_bounds__(NTHR, 1)
afm_kernel(const float* __restrict__ x,    // [B, F, E]
           const float* __restrict__ ww,   // [A, E]
           const float* __restrict__ wb,   // [A]
           const float* __restrict__ hw,   // [1, A]
           const float* __restrict__ pw,   // [1, E]
           const float* __restrict__ pb,   // [1]
           float* __restrict__ out)        // [B]
{
    __shared__ float   xs[NF * XST];      // ~21.1 KB
    __shared__ float   scs4[4][NPP];      // per-aslot partial scores
    __shared__ float   scs[NPP];
    __shared__ float   dvs[NPP];          // d[p] = hp_p . p_w
    __shared__ float   pws[ED];
    __shared__ uint8_t pis[NPP], pjs[NPP];
    __shared__ float   red[3 * NWRP];

    const int tid  = threadIdx.x;
    const int wid  = tid >> 5, lane = tid & 31;
    const int g     = wid >> 2;       // pair-group 0..2
    const int aslot = wid & 3;        // owns a-rows [aslot*32, aslot*32+32)
    const int q = lane >> 2, c = lane & 3;
    const int b = blockIdx.x;

    // ---- Stage x into padded smem ----
    const float* xg = x + (size_t)b * (NF * ED);
    for (int idx = tid; idx < NF * ED; idx += NTHR)
        xs[(idx >> 7) * XST + (idx & 127)] = xg[idx];
    for (int e = tid; e < ED; e += NTHR) pws[e] = pw[e];

    // ---- Pair index tables (triu i<j, i-major) ----
    for (int p = tid; p < NPP; p += NTHR) {
        if (p < NP) {
            int i = 0, rem = p;
            while (rem >= NF - 1 - i) { rem -= NF - 1 - i; i++; }
            pis[p] = (uint8_t)i; pjs[p] = (uint8_t)(i + 1 + rem);
        } else { pis[p] = 0; pjs[p] = 1; }
    }

    // ---- W fragments: register-stationary for this warp's 32 a-rows ----
    const int A0 = aslot * 32;
    uint32_t wA[2][16][4];
    #pragma unroll
    for (int mt = 0; mt < 2; mt++) {
        #pragma unroll
        for (int s = 0; s < 16; s++) {
            int r0 = (A0 + mt * 16 + q) * ED;
            int r1 = r0 + 8 * ED;
            int k0 = s * 8 + c;
            wA[mt][s][0] = tf32_of(ww[r0 + k0]);
            wA[mt][s][1] = tf32_of(ww[r1 + k0]);
            wA[mt][s][2] = tf32_of(ww[r0 + k0 + 4]);
            wA[mt][s][3] = tf32_of(ww[r1 + k0 + 4]);
        }
    }
    float wbr[4], hr[4];
    #pragma unroll
    for (int u = 0; u < 4; u++) {
        wbr[u] = wb[A0 + u * 8 + q];
        hr[u]  = hw[A0 + u * 8 + q];
    }

    __syncthreads();

    // ---- Main loop: n-tiles of 8 pairs; group g covers [g*33, min(g*33+33, 98)) ----
    const int nt0 = g * 33;
    const int nt1 = (g == 2) ? 98 : nt0 + 33;
    for (int nt = nt0; nt < nt1; nt++) {
        const int p = nt * 8 + q;                 // this quad's pair (B col)
        const float* xi = &xs[(int)pis[p] * XST + c];
        const float* xj = &xs[(int)pjs[p] * XST + c];

        float acc0[4] = {0.f, 0.f, 0.f, 0.f};
        float acc1[4] = {0.f, 0.f, 0.f, 0.f};
        // Interleaved build + MMA: brg live registers = 2 per step
        #pragma unroll
        for (int s = 0; s < 16; s++) {
            uint32_t b0 = tf32_of(xi[8 * s]     * xj[8 * s]);      // e = 8s + c
            uint32_t b1 = tf32_of(xi[8 * s + 4] * xj[8 * s + 4]);  // e = 8s + 4 + c
            mma8(acc0, wA[0][s], b0, b1);
            mma8(acc1, wA[1][s], b0, b1);
        }

        // Fused epilogue: partial score = sum over this warp's 32 a of h*relu(.+wb)
        float s0 = fmaxf(acc0[0] + wbr[0], 0.f) * hr[0]
                 + fmaxf(acc0[2] + wbr[1], 0.f) * hr[1]
                 + fmaxf(acc1[0] + wbr[2], 0.f) * hr[2]
                 + fmaxf(acc1[2] + wbr[3], 0.f) * hr[3];
        float s1 = fmaxf(acc0[1] + wbr[0], 0.f) * hr[0]
                 + fmaxf(acc0[3] + wbr[1], 0.f) * hr[1]
                 + fmaxf(acc1[1] + wbr[2], 0.f) * hr[2]
                 + fmaxf(acc1[3] + wbr[3], 0.f) * hr[3];
        #pragma unroll
        for (int o = 4; o <= 16; o <<= 1) {
            s0 += __shfl_xor_sync(0xffffffffu, s0, o);
            s1 += __shfl_xor_sync(0xffffffffu, s1, o);
        }
        if (lane < 4) {
            scs4[aslot][nt * 8 + 2 * lane]     = s0;
            scs4[aslot][nt * 8 + 2 * lane + 1] = s1;
        }
    }

    // ---- d[p] = sum_e x_i,e * x_j,e * pw_e (warp per pair) ----
    for (int p = wid; p < NP; p += NWRP) {
        const float* xi = &xs[(int)pis[p] * XST];
        const float* xj = &xs[(int)pjs[p] * XST];
        float a = 0.f;
        #pragma unroll
        for (int k = 0; k < 4; k++) {
            int e = lane + 32 * k;
            a = fmaf(xi[e] * xj[e], pws[e], a);
        }
        #pragma unroll
        for (int o = 16; o; o >>= 1) a += __shfl_xor_sync(0xffffffffu, a, o);
        if (lane == 0) dvs[p] = a;
    }
    __syncthreads();

    for (int p = tid; p < NP; p += NTHR)
        scs[p] = scs4[0][p] + scs4[1][p] + scs4[2][p] + scs4[3][p];
    __syncthreads();

    // ---- Softmax over pairs + weighted sum (h_b softmax-invariant, dropped) ----
    float lmax = -3.4e38f;
    for (int p = tid; p < NP; p += NTHR) lmax = fmaxf(lmax, scs[p]);
    #pragma unroll
    for (int o = 16; o; o >>= 1) lmax = fmaxf(lmax, __shfl_xor_sync(0xffffffffu, lmax, o));
    if (lane == 0) red[wid] = lmax;
    __syncthreads();
    float m = red[0];
    #pragma unroll
    for (int w = 1; w < NWRP; w++) m = fmaxf(m, red[w]);

    float se = 0.f, sd = 0.f;
    for (int p = tid; p < NP; p += NTHR) {
        float e = __expf(scs[p] - m);
        se += e;
        sd = fmaf(e, dvs[p], sd);
    }
    #pragma unroll
    for (int o = 16; o; o >>= 1) {
        se += __shfl_xor_sync(0xffffffffu, se, o);
        sd += __shfl_xor_sync(0xffffffffu, sd, o);
    }
    if (lane == 0) { red[NWRP + wid] = se; red[2 * NWRP + wid] = sd; }
    __syncthreads();
    if (tid == 0) {
        float S = 0.f, D = 0.f;
        #pragma unroll
        for (int w = 0; w < NWRP; w++) { S += red[NWRP + w]; D += red[2 * NWRP + w]; }
        out[b] = D / S + pb[0];
    }
}

extern "C" void kernel_launch(void* const* d_in, const int* in_sizes, int n_in,
                              void* d_out, int out_size) {
    const float* x  = (const float*)d_in[0];
    const float* ww = (const float*)d_in[1];
    const float* wb = (const float*)d_in[2];
    const float* hw = (const float*)d_in[3];
    // d_in[4] = attn_h_b: uniform shift on scores, softmax-invariant -> unused
    const float* pw = (const float*)d_in[5];
    const float* pb = (const float*)d_in[6];
    float* out = (float*)d_out;

    int B = in_sizes[0] / (NF * ED);
    afm_kernel<<<B, NTHR>>>(x, ww, wb, hw, pw, pb, out);
}